// round 1
// baseline (speedup 1.0000x reference)
#include <cuda_runtime.h>
#include <math_constants.h>

#define NTOK 8192
#define EDIM 64
#define BM 64
#define BN 128
#define SCALE 0.35355339059327373f   // 1/sqrt(8)

__device__ float g_qq[NTOK*EDIM];
__device__ float g_kk[NTOK*EDIM];
__device__ float g_vv[NTOK*EDIM];
__device__ float g_ov[NTOK*EDIM];

// ---------------- Kernel 1: QKV projection + quantum map ----------------
// q = x @ Wq^T + bq ; q_q = cos(theta) * cos(q)   (same for k, v)
__global__ void __launch_bounds__(256) qkv_kernel(
    const float* __restrict__ x,
    const float* __restrict__ wq, const float* __restrict__ bq,
    const float* __restrict__ wk, const float* __restrict__ bk,
    const float* __restrict__ wv, const float* __restrict__ bv,
    const float* __restrict__ theta)
{
    extern __shared__ float sm1[];
    float* wt   = sm1;           // [3][64][65] row-major w/ pad: 12480 floats
    float* bias = sm1 + 12480;   // [3][64]
    float* cth  = sm1 + 12672;   // [64]
    float* xs   = sm1 + 12736;   // [32][64]

    const int tid = threadIdx.x;
    {
        const float* ws0 = wq; const float* ws1 = wk; const float* ws2 = wv;
        for (int i = tid; i < 4096; i += 256) {
            int e = i >> 6, d = i & 63;
            wt[(0*64 + e)*65 + d] = ws0[i];
            wt[(1*64 + e)*65 + d] = ws1[i];
            wt[(2*64 + e)*65 + d] = ws2[i];
        }
        if (tid < 64) {
            bias[0*64 + tid] = bq[tid];
            bias[1*64 + tid] = bk[tid];
            bias[2*64 + tid] = bv[tid];
            cth[tid] = __cosf(theta[tid]);
        }
    }
    const int row0 = blockIdx.x * 32;
    for (int i = tid; i < 32*64; i += 256)
        xs[i] = x[row0*64 + i];
    __syncthreads();

    for (int t = tid; t < 3*32*64; t += 256) {
        int m   = t >> 11;
        int rem = t & 2047;
        int row = rem >> 6, col = rem & 63;
        float acc = bias[m*64 + col];
        const float* wrow = &wt[(m*64 + col)*65];
        const float* xrow = &xs[row*64];
        #pragma unroll
        for (int d = 0; d < 64; d++)
            acc = fmaf(xrow[d], wrow[d], acc);
        float val = cth[col] * __cosf(acc);
        float* op = (m == 0) ? g_qq : ((m == 1) ? g_kk : g_vv);
        op[(row0 + row)*64 + col] = val;
    }
}

// ---------------- Kernel 2: flash attention over flattened N=8192 ----------------
// 256 threads; S tile 64x128 (micro 4x8), O tile 64x64 (micro 4x4).
// tr = tid>>4 owns rows tr*4..+3 ; tc = tid&15 owns S-cols tc*8..+7 / O-dims tc*4..+3.
__global__ void __launch_bounds__(256, 1) flash_kernel()
{
    extern __shared__ float sm[];
    float* qT = sm;             // [64 k][68]  : qT[k*68 + r]   (scaled Q, transposed)
    float* kT = sm + 4352;      // [64 k][132] : kT[k*132 + c]  (K transposed)
    float* vS = sm + 12800;     // [128 c][68] : vS[c*68 + d]
    float* pS = sm + 21504;     // [64 r][132] : pS[r*132 + c]

    const int tid = threadIdx.x;
    const int tr = tid >> 4;
    const int tc = tid & 15;
    const int qb = blockIdx.x;

    for (int i = tid; i < BM*EDIM; i += 256) {
        int n = i >> 6, d = i & 63;
        qT[d*68 + n] = g_qq[(qb*BM + n)*EDIM + d] * SCALE;
    }

    float mrun[4], lrun[4], o[4][4];
    #pragma unroll
    for (int i = 0; i < 4; i++) {
        mrun[i] = -CUDART_INF_F; lrun[i] = 0.f;
        #pragma unroll
        for (int dd = 0; dd < 4; dd++) o[i][dd] = 0.f;
    }

    for (int kb = 0; kb < NTOK/BN; kb++) {
        __syncthreads();   // prior PV reads of vS/pS done before overwrite
        #pragma unroll 4
        for (int i = tid; i < BN*EDIM; i += 256) {
            int n = i >> 6, d = i & 63;
            int g = (kb*BN + n)*EDIM + d;
            kT[d*132 + n] = g_kk[g];
            vS[n*68 + d]  = g_vv[g];
        }
        __syncthreads();

        // ---- S = (Q*scale) K^T ----
        float s[4][8];
        #pragma unroll
        for (int i = 0; i < 4; i++)
            #pragma unroll
            for (int j = 0; j < 8; j++) s[i][j] = 0.f;

        #pragma unroll 8
        for (int k = 0; k < EDIM; k++) {
            float4 a  = *reinterpret_cast<float4*>(&qT[k*68  + tr*4]);
            float4 b0 = *reinterpret_cast<float4*>(&kT[k*132 + tc*8]);
            float4 b1 = *reinterpret_cast<float4*>(&kT[k*132 + tc*8 + 4]);
            float aa[4] = {a.x, a.y, a.z, a.w};
            float bb[8] = {b0.x, b0.y, b0.z, b0.w, b1.x, b1.y, b1.z, b1.w};
            #pragma unroll
            for (int i = 0; i < 4; i++)
                #pragma unroll
                for (int j = 0; j < 8; j++)
                    s[i][j] = fmaf(aa[i], bb[j], s[i][j]);
        }

        // ---- online softmax (row stats across the 16-lane tc group) ----
        #pragma unroll
        for (int i = 0; i < 4; i++) {
            float tm = s[i][0];
            #pragma unroll
            for (int j = 1; j < 8; j++) tm = fmaxf(tm, s[i][j]);
            #pragma unroll
            for (int w = 1; w < 16; w <<= 1)
                tm = fmaxf(tm, __shfl_xor_sync(0xffffffffu, tm, w));
            float mnew  = fmaxf(mrun[i], tm);
            float alpha = __expf(mrun[i] - mnew);
            float sum = 0.f;
            #pragma unroll
            for (int j = 0; j < 8; j++) {
                float p = __expf(s[i][j] - mnew);
                s[i][j] = p;
                sum += p;
            }
            #pragma unroll
            for (int w = 1; w < 16; w <<= 1)
                sum += __shfl_xor_sync(0xffffffffu, sum, w);
            lrun[i] = lrun[i]*alpha + sum;
            mrun[i] = mnew;
            #pragma unroll
            for (int dd = 0; dd < 4; dd++) o[i][dd] *= alpha;
        }

        // ---- stash P ----
        #pragma unroll
        for (int i = 0; i < 4; i++) {
            *reinterpret_cast<float4*>(&pS[(tr*4+i)*132 + tc*8]) =
                make_float4(s[i][0], s[i][1], s[i][2], s[i][3]);
            *reinterpret_cast<float4*>(&pS[(tr*4+i)*132 + tc*8 + 4]) =
                make_float4(s[i][4], s[i][5], s[i][6], s[i][7]);
        }
        __syncthreads();

        // ---- O += P V ----
        #pragma unroll 2
        for (int c4 = 0; c4 < BN/4; c4++) {
            float4 p[4], v[4];
            #pragma unroll
            for (int i = 0; i < 4; i++)
                p[i] = *reinterpret_cast<float4*>(&pS[(tr*4+i)*132 + c4*4]);
            #pragma unroll
            for (int cc = 0; cc < 4; cc++)
                v[cc] = *reinterpret_cast<float4*>(&vS[(c4*4+cc)*68 + tc*4]);
            #pragma unroll
            for (int i = 0; i < 4; i++) {
                float pp[4] = {p[i].x, p[i].y, p[i].z, p[i].w};
                #pragma unroll
                for (int cc = 0; cc < 4; cc++) {
                    o[i][0] = fmaf(pp[cc], v[cc].x, o[i][0]);
                    o[i][1] = fmaf(pp[cc], v[cc].y, o[i][1]);
                    o[i][2] = fmaf(pp[cc], v[cc].z, o[i][2]);
                    o[i][3] = fmaf(pp[cc], v[cc].w, o[i][3]);
                }
            }
        }
    }

    // ---- epilogue: divide by l, write O ----
    #pragma unroll
    for (int i = 0; i < 4; i++) {
        float inv = 1.f / lrun[i];
        int n = qb*BM + tr*4 + i;
        float4 r = make_float4(o[i][0]*inv, o[i][1]*inv, o[i][2]*inv, o[i][3]*inv);
        *reinterpret_cast<float4*>(&g_ov[n*EDIM + tc*4]) = r;
    }
}

// ---------------- Kernel 3: output projection ----------------
__global__ void __launch_bounds__(256) proj_kernel(
    const float* __restrict__ wo, const float* __restrict__ bo,
    float* __restrict__ out)
{
    __shared__ float wt[64*65];
    __shared__ float bs[64];
    __shared__ float os[32*64];
    const int tid = threadIdx.x;
    for (int i = tid; i < 4096; i += 256)
        wt[(i >> 6)*65 + (i & 63)] = wo[i];
    if (tid < 64) bs[tid] = bo[tid];
    const int row0 = blockIdx.x * 32;
    for (int i = tid; i < 2048; i += 256)
        os[i] = g_ov[row0*64 + i];
    __syncthreads();

    for (int t = tid; t < 2048; t += 256) {
        int row = t >> 6, col = t & 63;
        float acc = bs[col];
        const float* wrow = &wt[col*65];
        const float* orow = &os[row*64];
        #pragma unroll
        for (int d = 0; d < 64; d++)
            acc = fmaf(orow[d], wrow[d], acc);
        out[(row0 + row)*64 + col] = acc;
    }
}

// ---------------- launch ----------------
extern "C" void kernel_launch(void* const* d_in, const int* in_sizes, int n_in,
                              void* d_out, int out_size)
{
    const float* x  = (const float*)d_in[0];
    const float* wq = (const float*)d_in[1];
    const float* bq = (const float*)d_in[2];
    const float* wk = (const float*)d_in[3];
    const float* bk = (const float*)d_in[4];
    const float* wv = (const float*)d_in[5];
    const float* bv = (const float*)d_in[6];
    const float* th = (const float*)d_in[7];
    const float* wo = (const float*)d_in[8];
    const float* bo = (const float*)d_in[9];
    float* out = (float*)d_out;

    const int SM1_BYTES   = 14784 * 4;   // 59136 B
    const int FLASH_BYTES = 29952 * 4;   // 119808 B
    cudaFuncSetAttribute(qkv_kernel,  cudaFuncAttributeMaxDynamicSharedMemorySize, SM1_BYTES);
    cudaFuncSetAttribute(flash_kernel, cudaFuncAttributeMaxDynamicSharedMemorySize, FLASH_BYTES);

    qkv_kernel<<<NTOK/32, 256, SM1_BYTES>>>(x, wq, bq, wk, bk, wv, bv, th);
    flash_kernel<<<NTOK/BM, 256, FLASH_BYTES>>>();
    proj_kernel<<<NTOK/32, 256>>>(wo, bo, out);
}

// round 2
// speedup vs baseline: 1.0022x; 1.0022x over previous
#include <cuda_runtime.h>
#include <math_constants.h>

#define NTOK 8192
#define EDIM 64
#define BM 64
#define BN 128
#define SCALE 0.35355339059327373f   // 1/sqrt(8)

__device__ float g_qq[NTOK*EDIM];
__device__ float g_kk[NTOK*EDIM];
__device__ float g_vv[NTOK*EDIM];
__device__ float g_ov[NTOK*EDIM];

// ---------------- Kernel 1: QKV projection + quantum map ----------------
// q = x @ Wq^T + bq ; q_q = cos(theta) * cos(q)   (same for k, v)
__global__ void __launch_bounds__(256) qkv_kernel(
    const float* __restrict__ x,
    const float* __restrict__ wq, const float* __restrict__ bq,
    const float* __restrict__ wk, const float* __restrict__ bk,
    const float* __restrict__ wv, const float* __restrict__ bv,
    const float* __restrict__ theta)
{
    extern __shared__ float sm1[];
    float* wt   = sm1;           // [3][64][65] row-major w/ pad: 12480 floats
    float* bias = sm1 + 12480;   // [3][64]
    float* cth  = sm1 + 12672;   // [64]
    float* xs   = sm1 + 12736;   // [32][64]

    const int tid = threadIdx.x;
    {
        const float* ws0 = wq; const float* ws1 = wk; const float* ws2 = wv;
        for (int i = tid; i < 4096; i += 256) {
            int e = i >> 6, d = i & 63;
            wt[(0*64 + e)*65 + d] = ws0[i];
            wt[(1*64 + e)*65 + d] = ws1[i];
            wt[(2*64 + e)*65 + d] = ws2[i];
        }
        if (tid < 64) {
            bias[0*64 + tid] = bq[tid];
            bias[1*64 + tid] = bk[tid];
            bias[2*64 + tid] = bv[tid];
            cth[tid] = __cosf(theta[tid]);
        }
    }
    const int row0 = blockIdx.x * 32;
    for (int i = tid; i < 32*64; i += 256)
        xs[i] = x[row0*64 + i];
    __syncthreads();

    for (int t = tid; t < 3*32*64; t += 256) {
        int m   = t >> 11;
        int rem = t & 2047;
        int row = rem >> 6, col = rem & 63;
        float acc = bias[m*64 + col];
        const float* wrow = &wt[(m*64 + col)*65];
        const float* xrow = &xs[row*64];
        #pragma unroll
        for (int d = 0; d < 64; d++)
            acc = fmaf(xrow[d], wrow[d], acc);
        float val = cth[col] * __cosf(acc);
        float* op = (m == 0) ? g_qq : ((m == 1) ? g_kk : g_vv);
        op[(row0 + row)*64 + col] = val;
    }
}

// ---------------- Kernel 2: flash attention over flattened N=8192 ----------------
// 256 threads; S tile 64x128 (micro 4x8), O tile 64x64 (micro 4x4).
// tr = tid>>4 owns rows tr*4..+3 ; tc = tid&15 owns S-cols tc*8..+7 / O-dims tc*4..+3.
__global__ void __launch_bounds__(256, 1) flash_kernel()
{
    extern __shared__ float sm[];
    float* qT = sm;             // [64 k][68]  : qT[k*68 + r]   (scaled Q, transposed)
    float* kT = sm + 4352;      // [64 k][132] : kT[k*132 + c]  (K transposed)
    float* vS = sm + 12800;     // [128 c][68] : vS[c*68 + d]
    float* pS = sm + 21504;     // [64 r][132] : pS[r*132 + c]

    const int tid = threadIdx.x;
    const int tr = tid >> 4;
    const int tc = tid & 15;
    const int qb = blockIdx.x;

    for (int i = tid; i < BM*EDIM; i += 256) {
        int n = i >> 6, d = i & 63;
        qT[d*68 + n] = g_qq[(qb*BM + n)*EDIM + d] * SCALE;
    }

    float mrun[4], lrun[4], o[4][4];
    #pragma unroll
    for (int i = 0; i < 4; i++) {
        mrun[i] = -CUDART_INF_F; lrun[i] = 0.f;
        #pragma unroll
        for (int dd = 0; dd < 4; dd++) o[i][dd] = 0.f;
    }

    for (int kb = 0; kb < NTOK/BN; kb++) {
        __syncthreads();   // prior PV reads of vS/pS done before overwrite
        #pragma unroll 4
        for (int i = tid; i < BN*EDIM; i += 256) {
            int n = i >> 6, d = i & 63;
            int g = (kb*BN + n)*EDIM + d;
            kT[d*132 + n] = g_kk[g];
            vS[n*68 + d]  = g_vv[g];
        }
        __syncthreads();

        // ---- S = (Q*scale) K^T ----
        float s[4][8];
        #pragma unroll
        for (int i = 0; i < 4; i++)
            #pragma unroll
            for (int j = 0; j < 8; j++) s[i][j] = 0.f;

        #pragma unroll 8
        for (int k = 0; k < EDIM; k++) {
            float4 a  = *reinterpret_cast<float4*>(&qT[k*68  + tr*4]);
            float4 b0 = *reinterpret_cast<float4*>(&kT[k*132 + tc*8]);
            float4 b1 = *reinterpret_cast<float4*>(&kT[k*132 + tc*8 + 4]);
            float aa[4] = {a.x, a.y, a.z, a.w};
            float bb[8] = {b0.x, b0.y, b0.z, b0.w, b1.x, b1.y, b1.z, b1.w};
            #pragma unroll
            for (int i = 0; i < 4; i++)
                #pragma unroll
                for (int j = 0; j < 8; j++)
                    s[i][j] = fmaf(aa[i], bb[j], s[i][j]);
        }

        // ---- online softmax (row stats across the 16-lane tc group) ----
        #pragma unroll
        for (int i = 0; i < 4; i++) {
            float tm = s[i][0];
            #pragma unroll
            for (int j = 1; j < 8; j++) tm = fmaxf(tm, s[i][j]);
            #pragma unroll
            for (int w = 1; w < 16; w <<= 1)
                tm = fmaxf(tm, __shfl_xor_sync(0xffffffffu, tm, w));
            float mnew  = fmaxf(mrun[i], tm);
            float alpha = __expf(mrun[i] - mnew);
            float sum = 0.f;
            #pragma unroll
            for (int j = 0; j < 8; j++) {
                float p = __expf(s[i][j] - mnew);
                s[i][j] = p;
                sum += p;
            }
            #pragma unroll
            for (int w = 1; w < 16; w <<= 1)
                sum += __shfl_xor_sync(0xffffffffu, sum, w);
            lrun[i] = lrun[i]*alpha + sum;
            mrun[i] = mnew;
            #pragma unroll
            for (int dd = 0; dd < 4; dd++) o[i][dd] *= alpha;
        }

        // ---- stash P ----
        #pragma unroll
        for (int i = 0; i < 4; i++) {
            *reinterpret_cast<float4*>(&pS[(tr*4+i)*132 + tc*8]) =
                make_float4(s[i][0], s[i][1], s[i][2], s[i][3]);
            *reinterpret_cast<float4*>(&pS[(tr*4+i)*132 + tc*8 + 4]) =
                make_float4(s[i][4], s[i][5], s[i][6], s[i][7]);
        }
        __syncthreads();

        // ---- O += P V ----
        #pragma unroll 2
        for (int c4 = 0; c4 < BN/4; c4++) {
            float4 p[4], v[4];
            #pragma unroll
            for (int i = 0; i < 4; i++)
                p[i] = *reinterpret_cast<float4*>(&pS[(tr*4+i)*132 + c4*4]);
            #pragma unroll
            for (int cc = 0; cc < 4; cc++)
                v[cc] = *reinterpret_cast<float4*>(&vS[(c4*4+cc)*68 + tc*4]);
            #pragma unroll
            for (int i = 0; i < 4; i++) {
                float pp[4] = {p[i].x, p[i].y, p[i].z, p[i].w};
                #pragma unroll
                for (int cc = 0; cc < 4; cc++) {
                    o[i][0] = fmaf(pp[cc], v[cc].x, o[i][0]);
                    o[i][1] = fmaf(pp[cc], v[cc].y, o[i][1]);
                    o[i][2] = fmaf(pp[cc], v[cc].z, o[i][2]);
                    o[i][3] = fmaf(pp[cc], v[cc].w, o[i][3]);
                }
            }
        }
    }

    // ---- epilogue: divide by l, write O ----
    #pragma unroll
    for (int i = 0; i < 4; i++) {
        float inv = 1.f / lrun[i];
        int n = qb*BM + tr*4 + i;
        float4 r = make_float4(o[i][0]*inv, o[i][1]*inv, o[i][2]*inv, o[i][3]*inv);
        *reinterpret_cast<float4*>(&g_ov[n*EDIM + tc*4]) = r;
    }
}

// ---------------- Kernel 3: output projection ----------------
__global__ void __launch_bounds__(256) proj_kernel(
    const float* __restrict__ wo, const float* __restrict__ bo,
    float* __restrict__ out)
{
    __shared__ float wt[64*65];
    __shared__ float bs[64];
    __shared__ float os[32*64];
    const int tid = threadIdx.x;
    for (int i = tid; i < 4096; i += 256)
        wt[(i >> 6)*65 + (i & 63)] = wo[i];
    if (tid < 64) bs[tid] = bo[tid];
    const int row0 = blockIdx.x * 32;
    for (int i = tid; i < 2048; i += 256)
        os[i] = g_ov[row0*64 + i];
    __syncthreads();

    for (int t = tid; t < 2048; t += 256) {
        int row = t >> 6, col = t & 63;
        float acc = bs[col];
        const float* wrow = &wt[col*65];
        const float* orow = &os[row*64];
        #pragma unroll
        for (int d = 0; d < 64; d++)
            acc = fmaf(orow[d], wrow[d], acc);
        out[(row0 + row)*64 + col] = acc;
    }
}

// ---------------- launch ----------------
extern "C" void kernel_launch(void* const* d_in, const int* in_sizes, int n_in,
                              void* d_out, int out_size)
{
    const float* x  = (const float*)d_in[0];
    const float* wq = (const float*)d_in[1];
    const float* bq = (const float*)d_in[2];
    const float* wk = (const float*)d_in[3];
    const float* bk = (const float*)d_in[4];
    const float* wv = (const float*)d_in[5];
    const float* bv = (const float*)d_in[6];
    const float* th = (const float*)d_in[7];
    const float* wo = (const float*)d_in[8];
    const float* bo = (const float*)d_in[9];
    float* out = (float*)d_out;

    const int SM1_BYTES   = 14784 * 4;   // 59136 B
    const int FLASH_BYTES = 29952 * 4;   // 119808 B
    cudaFuncSetAttribute(qkv_kernel,  cudaFuncAttributeMaxDynamicSharedMemorySize, SM1_BYTES);
    cudaFuncSetAttribute(flash_kernel, cudaFuncAttributeMaxDynamicSharedMemorySize, FLASH_BYTES);

    qkv_kernel<<<NTOK/32, 256, SM1_BYTES>>>(x, wq, bq, wk, bk, wv, bv, th);
    flash_kernel<<<NTOK/BM, 256, FLASH_BYTES>>>();
    proj_kernel<<<NTOK/32, 256>>>(wo, bo, out);
}

// round 4
// speedup vs baseline: 3.9581x; 3.9496x over previous
#include <cuda_runtime.h>
#include <cuda_bf16.h>
#include <cstdint>

#define NTOK 8192
#define EDIM 64
#define SCALE 0.35355339059327373f   // 1/sqrt(8)

// packed bf16x2 words: [row][32 words], swizzled within 128B rows for ldmatrix.
__device__ uint32_t g_qh[NTOK*32], g_ql[NTOK*32];
__device__ uint32_t g_kh[NTOK*32], g_kl[NTOK*32];
__device__ uint32_t g_vh[NTOK*32], g_vl[NTOK*32];
__device__ float    g_ov[NTOK*EDIM];

// ======================= helpers =======================
__device__ __forceinline__ uint32_t smem_u32(const void* p) {
    uint32_t a;
    asm("{ .reg .u64 t; cvta.to.shared.u64 t, %1; cvt.u32.u64 %0, t; }" : "=r"(a) : "l"(p));
    return a;
}
__device__ __forceinline__ void cp16(uint32_t dst, const void* src) {
    asm volatile("{ .reg .u64 g; cvta.to.global.u64 g, %1; cp.async.cg.shared.global [%0], [g], 16; }"
                 :: "r"(dst), "l"(src) : "memory");
}
#define CP_COMMIT() asm volatile("cp.async.commit_group;" ::: "memory")
#define CP_WAIT(n)  asm volatile("cp.async.wait_group %0;" :: "n"(n) : "memory")

#define LDSM4(r0,r1,r2,r3,a) \
    asm volatile("ldmatrix.sync.aligned.m8n8.x4.shared.b16 {%0,%1,%2,%3}, [%4];" \
        : "=r"(r0), "=r"(r1), "=r"(r2), "=r"(r3) : "r"(a))
#define LDSM4T(r0,r1,r2,r3,a) \
    asm volatile("ldmatrix.sync.aligned.m8n8.x4.trans.shared.b16 {%0,%1,%2,%3}, [%4];" \
        : "=r"(r0), "=r"(r1), "=r"(r2), "=r"(r3) : "r"(a))

#define MMA(c, a, b0, b1) \
    asm volatile("mma.sync.aligned.m16n8k16.row.col.f32.bf16.bf16.f32 " \
        "{%0,%1,%2,%3}, {%4,%5,%6,%7}, {%8,%9}, {%0,%1,%2,%3};" \
        : "+f"((c)[0]), "+f"((c)[1]), "+f"((c)[2]), "+f"((c)[3]) \
        : "r"((a)[0]), "r"((a)[1]), "r"((a)[2]), "r"((a)[3]), "r"(b0), "r"(b1))

// swizzled smem address: tile rows are 128B; 16B chunk index XOR (row&7).
__device__ __forceinline__ uint32_t swadr(uint32_t base, int row, int bytecol) {
    return base + row*128 + ((((bytecol >> 4) ^ (row & 7)) << 4));
}

__device__ __forceinline__ void packhl(float a, float b, uint32_t& h, uint32_t& l) {
    __nv_bfloat16 ah = __float2bfloat16(a), bh = __float2bfloat16(b);
    float ra = a - __bfloat162float(ah), rb = b - __bfloat162float(bh);
    __nv_bfloat16 al = __float2bfloat16(ra), bl = __float2bfloat16(rb);
    h = (uint32_t)__bfloat16_as_ushort(ah) | ((uint32_t)__bfloat16_as_ushort(bh) << 16);
    l = (uint32_t)__bfloat16_as_ushort(al) | ((uint32_t)__bfloat16_as_ushort(bl) << 16);
}

// smem layout: sQ hi 0..8K, sQ lo 8K..16K; buffers at 16K: per buf 32KB = [Kh|Kl|Vh|Vl] 8KB each
#define SBUF(b)    (16384 + (b)*32768)
#define SMEM_FLASH 81920

// ---------------- Kernel 1: QKV projection + quantum map + bf16 hi/lo packing ----------------
__global__ void __launch_bounds__(256) qkv_kernel(
    const float* __restrict__ x,
    const float* __restrict__ wq, const float* __restrict__ bq,
    const float* __restrict__ wk, const float* __restrict__ bk,
    const float* __restrict__ wv, const float* __restrict__ bv,
    const float* __restrict__ theta)
{
    __shared__ float wt[64*65];
    __shared__ float xs[32*64];
    __shared__ float bs[64];
    __shared__ float cs[64];
    const int tid = threadIdx.x;
    const int m = blockIdx.y;
    const int row0 = blockIdx.x * 32;

    const float* w  = (m == 0) ? wq : ((m == 1) ? wk : wv);
    const float* bb = (m == 0) ? bq : ((m == 1) ? bk : bv);
    for (int i = tid; i < 4096; i += 256)
        wt[(i >> 6)*65 + (i & 63)] = w[i];
    if (tid < 64) {
        bs[tid] = bb[tid];
        cs[tid] = ((m == 0) ? SCALE : 1.0f) * __cosf(theta[tid]);
    }
    for (int i = tid; i < 2048; i += 256)
        xs[i] = x[row0*64 + i];
    __syncthreads();

    for (int it = 0; it < 4; it++) {
        int idx = it*256 + tid;
        int row = idx >> 5, cp = idx & 31;     // column pair cp -> cols 2cp, 2cp+1
        float a0 = bs[2*cp], a1 = bs[2*cp + 1];
        const float* w0 = &wt[(2*cp)*65];
        const float* w1 = &wt[(2*cp + 1)*65];
        const float* xr = &xs[row*64];
        #pragma unroll
        for (int d = 0; d < 64; d++) {
            float xv = xr[d];
            a0 = fmaf(xv, w0[d], a0);
            a1 = fmaf(xv, w1[d], a1);
        }
        float v0 = cs[2*cp]     * __cosf(a0);
        float v1 = cs[2*cp + 1] * __cosf(a1);
        uint32_t hw, lw;
        packhl(v0, v1, hw, lw);
        int gr = row0 + row;
        int wd = ((((cp >> 2) ^ (gr & 7)) << 2) | (cp & 3));   // swizzled word index
        if (m == 0)      { g_qh[gr*32 + wd] = hw; g_ql[gr*32 + wd] = lw; }
        else if (m == 1) { g_kh[gr*32 + wd] = hw; g_kl[gr*32 + wd] = lw; }
        else             { g_vh[gr*32 + wd] = hw; g_vl[gr*32 + wd] = lw; }
    }
}

// ---------------- tile copy: 64 keys x (Kh,Kl,Vh,Vl), all pre-swizzled ----------------
__device__ __forceinline__ void copy_tile(uint32_t sb, int tid, int buf, int kb) {
    #pragma unroll
    for (int j = 0; j < 16; j++) {
        int c = j*128 + tid;
        int arr = c >> 9;           // 0:kh 1:kl 2:vh 3:vl  (constant per j)
        int rem = c & 511;
        int row = rem >> 3, ch = rem & 7;
        const uint32_t* sp = (arr == 0) ? g_kh : (arr == 1) ? g_kl : (arr == 2) ? g_vh : g_vl;
        cp16(sb + SBUF(buf) + arr*8192 + row*128 + ch*16,
             sp + (size_t)(kb*64 + row)*32 + ch*4);
    }
}

// ---------------- Kernel 2: mma.sync flash attention (no-max softmax) ----------------
__global__ void __launch_bounds__(128, 1) flash_kernel()
{
    extern __shared__ char smem[];
    uint32_t sb = smem_u32(smem);
    const int tid  = threadIdx.x;
    const int wid  = tid >> 5;
    const int lane = tid & 31;
    const int qb   = blockIdx.x;           // 64 q-rows per CTA

    // ---- prologue copies: Q, tile0, tile1 ----
    #pragma unroll
    for (int j = 0; j < 8; j++) {
        int c = j*128 + tid;
        int arr = c >> 9;                   // 0:qh 1:ql
        int rem = c & 511;
        int row = rem >> 3, ch = rem & 7;
        const uint32_t* sp = arr ? g_ql : g_qh;
        cp16(sb + arr*8192 + row*128 + ch*16,
             sp + (size_t)(qb*64 + row)*32 + ch*4);
    }
    CP_COMMIT();
    copy_tile(sb, tid, 0, 0); CP_COMMIT();
    copy_tile(sb, tid, 1, 1); CP_COMMIT();
    CP_WAIT(2);                  // Q group done
    __syncthreads();

    // ---- Q A-fragments (persistent) ----
    uint32_t qh[4][4], ql[4][4];
    {
        const int m0 = wid*16;
        #pragma unroll
        for (int kc = 0; kc < 4; kc++) {
            int row = m0 + (lane & 15);
            int bc  = 32*kc + (lane >> 4)*16;
            LDSM4(qh[kc][0], qh[kc][1], qh[kc][2], qh[kc][3], swadr(sb,        row, bc));
            LDSM4(ql[kc][0], ql[kc][1], ql[kc][2], ql[kc][3], swadr(sb + 8192, row, bc));
        }
    }

    float o[8][4];
    #pragma unroll
    for (int nb = 0; nb < 8; nb++)
        #pragma unroll
        for (int i = 0; i < 4; i++) o[nb][i] = 0.f;
    float lg = 0.f, lg8 = 0.f;

    #pragma unroll 1
    for (int kb = 0; kb < 128; kb++) {
        const int b = kb & 1;
        if (kb < 126) { CP_WAIT(1); } else { CP_WAIT(0); }
        __syncthreads();

        const uint32_t kbh = sb + SBUF(b);
        const uint32_t kbl = kbh + 8192;
        const uint32_t vbh = kbh + 16384;
        const uint32_t vbl = kbh + 24576;

        // ---- S = Q K^T (3-term hi/lo) ----
        float sc[8][4];
        #pragma unroll
        for (int nb = 0; nb < 8; nb++)
            #pragma unroll
            for (int i = 0; i < 4; i++) sc[nb][i] = 0.f;

        #pragma unroll
        for (int kcp = 0; kcp < 2; kcp++) {
            uint32_t kf[8][4];
            const int li = lane & 7, ls = lane >> 3;
            #pragma unroll
            for (int nb = 0; nb < 8; nb++)
                LDSM4(kf[nb][0], kf[nb][1], kf[nb][2], kf[nb][3],
                      swadr(kbh, nb*8 + li, 64*kcp + ls*16));
            #pragma unroll
            for (int k2 = 0; k2 < 2; k2++) {
                const int kc = kcp*2 + k2;
                #pragma unroll
                for (int nb = 0; nb < 8; nb++) MMA(sc[nb], qh[kc], kf[nb][2*k2], kf[nb][2*k2+1]);
                #pragma unroll
                for (int nb = 0; nb < 8; nb++) MMA(sc[nb], ql[kc], kf[nb][2*k2], kf[nb][2*k2+1]);
            }
            #pragma unroll
            for (int nb = 0; nb < 8; nb++)
                LDSM4(kf[nb][0], kf[nb][1], kf[nb][2], kf[nb][3],
                      swadr(kbl, nb*8 + li, 64*kcp + ls*16));
            #pragma unroll
            for (int k2 = 0; k2 < 2; k2++) {
                const int kc = kcp*2 + k2;
                #pragma unroll
                for (int nb = 0; nb < 8; nb++) MMA(sc[nb], qh[kc], kf[nb][2*k2], kf[nb][2*k2+1]);
            }
        }

        // ---- softmax (no max; bounded scores) + pack P into A-frags ----
        uint32_t ph[4][4], pl[4][4];
        #pragma unroll
        for (int nb = 0; nb < 8; nb++) {
            float e0 = __expf(sc[nb][0]), e1 = __expf(sc[nb][1]);
            float e2 = __expf(sc[nb][2]), e3 = __expf(sc[nb][3]);
            lg  += e0 + e1;
            lg8 += e2 + e3;
            const int kc = nb >> 1, rb = (nb & 1) * 2;
            packhl(e0, e1, ph[kc][rb + 0], pl[kc][rb + 0]);
            packhl(e2, e3, ph[kc][rb + 1], pl[kc][rb + 1]);
        }

        // ---- O += P V (3-term hi/lo) ----
        const int li = lane & 7, lr = (lane >> 3) & 1, lc = lane >> 4;
        #pragma unroll
        for (int kc = 0; kc < 4; kc++) {
            uint32_t vf[4][4];
            #pragma unroll
            for (int dp = 0; dp < 4; dp++)
                LDSM4T(vf[dp][0], vf[dp][1], vf[dp][2], vf[dp][3],
                       swadr(vbh, kc*16 + lr*8 + li, 32*dp + lc*16));
            #pragma unroll
            for (int nb = 0; nb < 8; nb++) MMA(o[nb], ph[kc], vf[nb>>1][(nb&1)*2], vf[nb>>1][(nb&1)*2+1]);
            #pragma unroll
            for (int nb = 0; nb < 8; nb++) MMA(o[nb], pl[kc], vf[nb>>1][(nb&1)*2], vf[nb>>1][(nb&1)*2+1]);
            #pragma unroll
            for (int dp = 0; dp < 4; dp++)
                LDSM4T(vf[dp][0], vf[dp][1], vf[dp][2], vf[dp][3],
                       swadr(vbl, kc*16 + lr*8 + li, 32*dp + lc*16));
            #pragma unroll
            for (int nb = 0; nb < 8; nb++) MMA(o[nb], ph[kc], vf[nb>>1][(nb&1)*2], vf[nb>>1][(nb&1)*2+1]);
        }

        __syncthreads();
        if (kb + 2 < 128) { copy_tile(sb, tid, b, kb + 2); CP_COMMIT(); }
    }

    // ---- epilogue: row-sum reduce across quad, normalize, store ----
    lg  += __shfl_xor_sync(0xffffffffu, lg, 1);
    lg  += __shfl_xor_sync(0xffffffffu, lg, 2);
    lg8 += __shfl_xor_sync(0xffffffffu, lg8, 1);
    lg8 += __shfl_xor_sync(0xffffffffu, lg8, 2);
    const float ig = 1.f/lg, ig8 = 1.f/lg8;
    const int g = lane >> 2, t = lane & 3;
    const int n = qb*64 + wid*16 + g;
    #pragma unroll
    for (int nb = 0; nb < 8; nb++) {
        int d = nb*8 + 2*t;
        *reinterpret_cast<float2*>(&g_ov[(size_t)n*64 + d])       = make_float2(o[nb][0]*ig,  o[nb][1]*ig);
        *reinterpret_cast<float2*>(&g_ov[(size_t)(n + 8)*64 + d]) = make_float2(o[nb][2]*ig8, o[nb][3]*ig8);
    }
}

// ---------------- Kernel 3: output projection ----------------
__global__ void __launch_bounds__(256) proj_kernel(
    const float* __restrict__ wo, const float* __restrict__ bo,
    float* __restrict__ out)
{
    __shared__ float wt[64*65];
    __shared__ float bs[64];
    __shared__ float os[32*64];
    const int tid = threadIdx.x;
    const int row0 = blockIdx.x * 32;
    for (int i = tid; i < 4096; i += 256)
        wt[(i >> 6)*65 + (i & 63)] = wo[i];
    if (tid < 64) bs[tid] = bo[tid];
    for (int i = tid; i < 2048; i += 256)
        os[i] = g_ov[(size_t)row0*64 + i];
    __syncthreads();

    for (int tI = tid; tI < 2048; tI += 256) {
        int row = tI >> 6, col = tI & 63;
        float acc = bs[col];
        const float* wrow = &wt[col*65];
        const float* orow = &os[row*64];
        #pragma unroll
        for (int d = 0; d < 64; d++)
            acc = fmaf(orow[d], wrow[d], acc);
        out[(row0 + row)*64 + col] = acc;
    }
}

// ---------------- launch ----------------
extern "C" void kernel_launch(void* const* d_in, const int* in_sizes, int n_in,
                              void* d_out, int out_size)
{
    const float* x  = (const float*)d_in[0];
    const float* wq = (const float*)d_in[1];
    const float* bq = (const float*)d_in[2];
    const float* wk = (const float*)d_in[3];
    const float* bk = (const float*)d_in[4];
    const float* wv = (const float*)d_in[5];
    const float* bv = (const float*)d_in[6];
    const float* th = (const float*)d_in[7];
    const float* wo = (const float*)d_in[8];
    const float* bo = (const float*)d_in[9];
    float* out = (float*)d_out;

    cudaFuncSetAttribute(flash_kernel, cudaFuncAttributeMaxDynamicSharedMemorySize, SMEM_FLASH);

    qkv_kernel<<<dim3(NTOK/32, 3), 256>>>(x, wq, bq, wk, bk, wv, bv, th);
    flash_kernel<<<128, 128, SMEM_FLASH>>>();
    proj_kernel<<<NTOK/32, 256>>>(wo, bo, out);
}